// round 15
// baseline (speedup 1.0000x reference)
#include <cuda_runtime.h>
#include <cuda_bf16.h>
#include <cuda_fp16.h>
#include <cstdint>

static constexpr int S_  = 2048;
static constexpr int B_  = 2;
static constexpr int E_  = 1024;
static constexpr int H_  = 16;
static constexpr int DH_ = 64;
static constexpr int MR_ = S_ * B_;   // 4096

// ---------------- scratch (device globals: no allocations allowed) ----------
__device__ float g_m [B_ * H_ * S_];
__device__ float g_il[B_ * H_ * S_];
__device__ __half g_P[(size_t)B_ * H_ * S_ * S_];       // tile-local softmax numerators, 256 MB
__device__ float  g_ml[(size_t)B_ * S_ * H_ * 32];      // running max per (row, 64-t tile), 16 MB
__device__ int    g_ctr[2];                              // dynamic work counters (proj, attn)
// bf16 hi/lo pools (mirrored layout in g_h / g_l)
static constexpr uint32_t OFF_QI = 0,        OFF_KI = 4u<<20,  OFF_VI = 8u<<20,  OFF_AT = 12u<<20;
static constexpr uint32_t OFF_QW = 16u<<20,  OFF_KW = 17u<<20, OFF_VW = 18u<<20, OFF_OW = 19u<<20;
static constexpr uint32_t OFF_QO = 20u<<20,  OFF_KO = 24u<<20, OFF_VO = 28u<<20;
__device__ __nv_bfloat16 g_h[32u << 20];
__device__ __nv_bfloat16 g_l[32u << 20];

// ===================== mma.sync helpers (sm_80 baseline PTX) =================
__device__ __forceinline__ uint32_t smem_u32(const void* p) {
    uint32_t a;
    asm("{ .reg .u64 t; cvta.to.shared.u64 t, %1; cvt.u32.u64 %0, t; }" : "=r"(a) : "l"(p));
    return a;
}
__device__ __forceinline__ void ldsm4(uint32_t* r, uint32_t addr) {
    asm volatile("ldmatrix.sync.aligned.m8n8.x4.shared.b16 {%0,%1,%2,%3}, [%4];"
                 : "=r"(r[0]), "=r"(r[1]), "=r"(r[2]), "=r"(r[3]) : "r"(addr));
}
__device__ __forceinline__ void ldsm4t(uint32_t* r, uint32_t addr) {
    asm volatile("ldmatrix.sync.aligned.m8n8.x4.trans.shared.b16 {%0,%1,%2,%3}, [%4];"
                 : "=r"(r[0]), "=r"(r[1]), "=r"(r[2]), "=r"(r[3]) : "r"(addr));
}
__device__ __forceinline__ void mma_bf16(float* c, const uint32_t* a, uint32_t b0, uint32_t b1) {
    asm volatile("mma.sync.aligned.m16n8k16.row.col.f32.bf16.bf16.f32 "
                 "{%0,%1,%2,%3}, {%4,%5,%6,%7}, {%8,%9}, {%0,%1,%2,%3};"
                 : "+f"(c[0]), "+f"(c[1]), "+f"(c[2]), "+f"(c[3])
                 : "r"(a[0]), "r"(a[1]), "r"(a[2]), "r"(a[3]), "r"(b0), "r"(b1));
}
__device__ __forceinline__ uint32_t packbf2(float lo, float hi) {
    uint32_t r;
    asm("cvt.rn.bf16x2.f32 %0, %1, %2;" : "=r"(r) : "f"(hi), "f"(lo));
    return r;
}
#define CP_ASYNC16(dst, src) \
    asm volatile("cp.async.ca.shared.global [%0], [%1], 16;" :: "r"(dst), "l"(src) : "memory")
#define CP_COMMIT() asm volatile("cp.async.commit_group;" ::: "memory")
#define CP_WAIT0()  asm volatile("cp.async.wait_group 0;" ::: "memory")
#define CP_WAIT1()  asm volatile("cp.async.wait_group 1;" ::: "memory")

// ============== fused split: all 7 fp32 tensors -> bf16 hi/lo pools ==========
// Also resets the dynamic-work counters (stream-ordered before their users).
__global__ __launch_bounds__(256) void split_all(
    const float* __restrict__ q_in, const float* __restrict__ k_in,
    const float* __restrict__ v_in, const float* __restrict__ q_w,
    const float* __restrict__ k_w,  const float* __restrict__ v_w,
    const float* __restrict__ o_w)
{
    if (blockIdx.x == 0 && threadIdx.x == 0) { g_ctr[0] = 0; g_ctr[1] = 0; }

    const int NI = MR_ * E_ / 8;      // 524288 chunks per input
    const int NW = E_ * E_ / 8;       // 131072 chunks per weight
    int i = blockIdx.x * blockDim.x + threadIdx.x;
    const float* src; uint32_t dst; int li;
    if      (i < NI)              { src = q_in; dst = OFF_QI; li = i; }
    else if (i < 2*NI)            { src = k_in; dst = OFF_KI; li = i - NI; }
    else if (i < 3*NI)            { src = v_in; dst = OFF_VI; li = i - 2*NI; }
    else if (i < 3*NI + NW)       { src = q_w;  dst = OFF_QW; li = i - 3*NI; }
    else if (i < 3*NI + 2*NW)     { src = k_w;  dst = OFF_KW; li = i - 3*NI - NW; }
    else if (i < 3*NI + 3*NW)     { src = v_w;  dst = OFF_VW; li = i - 3*NI - 2*NW; }
    else                          { src = o_w;  dst = OFF_OW; li = i - 3*NI - 3*NW; }

    float4 v0 = ((const float4*)src)[2*li], v1 = ((const float4*)src)[2*li+1];
    float x[8] = {v0.x, v0.y, v0.z, v0.w, v1.x, v1.y, v1.z, v1.w};
    uint4 h4, l4;
    uint32_t* hp = (uint32_t*)&h4; uint32_t* lp = (uint32_t*)&l4;
    #pragma unroll
    for (int p = 0; p < 4; p++) {
        uint32_t h = packbf2(x[2*p], x[2*p+1]);
        float xh = __uint_as_float(h << 16);
        float yh = __uint_as_float(h & 0xFFFF0000u);
        hp[p] = h;
        lp[p] = packbf2(x[2*p] - xh, x[2*p+1] - yh);
    }
    ((uint4*)(g_h + dst))[li] = h4;
    ((uint4*)(g_l + dst))[li] = l4;
}

// ===== bf16x3 GEMM tile body, cp.async 2-stage k-32 (R12-frozen schedule) ====
__device__ __forceinline__ void gemm_cpasync_body(
    int m0, int n0, uint32_t offA, uint32_t offW,
    const float* __restrict__ bias, float* __restrict__ C,
    __nv_bfloat16* __restrict__ Ch, __nv_bfloat16* __restrict__ Cl, float scale)
{
    extern __shared__ __align__(16) unsigned char sm[];
    const int tid = threadIdx.x, lane = tid & 31, wid = tid >> 5;
    const int wm = wid & 3, wn = wid >> 2;
    const uint32_t sb = smem_u32(sm);

    uint32_t offs[8], dofs[8];
    #pragma unroll
    for (int c = 0; c < 8; c++) {
        int g = c * 256 + tid;
        int part = g >> 10, idx = g & 1023, hl = idx >> 9, rc = idx & 511;
        int row = rc >> 2, ch = rc & 3;
        uint32_t o = (part ? offW : offA)
                   + (uint32_t)((part ? n0 : m0) + row) * E_ + ch * 8;
        offs[c] = o | (hl ? 0x80000000u : 0u);
        dofs[c] = (uint32_t)(part * 20480 + hl * 10240 + row * 80 + ch * 16);
    }

    #define ISSUE_STAGE(s, k0) do {                                            \
        uint32_t stb = sb + (s) * 40960;                                       \
        _Pragma("unroll")                                                      \
        for (int c = 0; c < 8; c++) {                                          \
            uint32_t o = offs[c];                                              \
            const __nv_bfloat16* base = (o & 0x80000000u) ? g_l : g_h;         \
            CP_ASYNC16(stb + dofs[c], base + (o & 0x7FFFFFFFu) + (k0));        \
        }                                                                      \
        CP_COMMIT();                                                           \
    } while (0)

    ISSUE_STAGE(0, 0);
    ISSUE_STAGE(1, 32);
    CP_WAIT1();
    __syncthreads();

    float acc[2][8][4] = {};
    const int lr = lane & 15, lkh = lane >> 4;

    for (int kb = 0; kb < 32; kb++) {
        int s = kb & 1;
        uint32_t Ab = sb + s * 40960;
        uint32_t Wb = Ab + 20480;
        #pragma unroll
        for (int ks = 0; ks < 2; ks++) {
            uint32_t aH[2][4], aL[2][4];
            #pragma unroll
            for (int i = 0; i < 2; i++) {
                uint32_t ad = Ab + (wm * 32 + i * 16 + lr) * 80 + ks * 32 + lkh * 16;
                ldsm4(aH[i], ad); ldsm4(aL[i], ad + 10240);
            }
            #pragma unroll
            for (int np = 0; np < 4; np++) {
                uint32_t wa = Wb + (wn * 64 + np * 16 + lr) * 80 + ks * 32 + lkh * 16;
                uint32_t wHf[4], wLf[4];
                ldsm4(wHf, wa); ldsm4(wLf, wa + 10240);
                #pragma unroll
                for (int i = 0; i < 2; i++)
                    #pragma unroll
                    for (int js = 0; js < 2; js++) {
                        int j = np * 2 + js;
                        mma_bf16(acc[i][j], aH[i], wHf[js], wHf[js + 2]);
                        mma_bf16(acc[i][j], aH[i], wLf[js], wLf[js + 2]);
                        mma_bf16(acc[i][j], aL[i], wHf[js], wHf[js + 2]);
                    }
            }
        }
        __syncthreads();
        if (kb + 2 < 32) {
            ISSUE_STAGE(s, (kb + 2) * 32);
            CP_WAIT1();
        } else {
            CP_WAIT0();
        }
        __syncthreads();
    }
    #undef ISSUE_STAGE

    #pragma unroll
    for (int i = 0; i < 2; i++) {
        int mrow = m0 + wm * 32 + i * 16 + (lane >> 2);
        #pragma unroll
        for (int j = 0; j < 8; j++) {
            int n = n0 + wn * 64 + j * 8 + (lane & 3) * 2;
            float c0 = acc[i][j][0] * scale, c1 = acc[i][j][1] * scale;
            float c2 = acc[i][j][2] * scale, c3 = acc[i][j][3] * scale;
            if (Ch) {
                uint32_t h0 = packbf2(c0, c1), h1 = packbf2(c2, c3);
                float e00 = __uint_as_float(h0 << 16), e01 = __uint_as_float(h0 & 0xFFFF0000u);
                float e10 = __uint_as_float(h1 << 16), e11 = __uint_as_float(h1 & 0xFFFF0000u);
                uint32_t l0 = packbf2(c0 - e00, c1 - e01);
                uint32_t l1 = packbf2(c2 - e10, c3 - e11);
                size_t i0 = (size_t)mrow * E_ + n, i1 = (size_t)(mrow + 8) * E_ + n;
                *(uint32_t*)&Ch[i0] = h0; *(uint32_t*)&Cl[i0] = l0;
                *(uint32_t*)&Ch[i1] = h1; *(uint32_t*)&Cl[i1] = l1;
            } else {
                float bx = 0.f, by = 0.f;
                if (bias) { float2 bv = *(const float2*)&bias[n]; bx = bv.x; by = bv.y; }
                *(float2*)&C[(size_t)mrow * E_ + n]       = make_float2(c0 + bx, c1 + by);
                *(float2*)&C[(size_t)(mrow + 8) * E_ + n] = make_float2(c2 + bx, c3 + by);
            }
        }
    }
}

// ---- persistent proj: 768 tiles pulled off g_ctr[0] by 304 resident blocks --
__global__ __launch_bounds__(256, 2) void proj3_persist()
{
    __shared__ int s_w;
    for (;;) {
        __syncthreads();                 // all warps done with previous tile
        if (threadIdx.x == 0) s_w = atomicAdd(&g_ctr[0], 1);
        __syncthreads();
        int w = s_w;
        if (w >= 768) return;
        int z = w >> 8, r = w & 255;
        int m0 = (r >> 3) * 128, n0 = (r & 7) * 128;
        if (z == 0)
            gemm_cpasync_body(m0, n0, OFF_QI, OFF_QW, nullptr, nullptr,
                              g_h + OFF_QO, g_l + OFF_QO, 0.125f);
        else if (z == 1)
            gemm_cpasync_body(m0, n0, OFF_KI, OFF_KW, nullptr, nullptr,
                              g_h + OFF_KO, g_l + OFF_KO, 1.0f);
        else
            gemm_cpasync_body(m0, n0, OFF_VI, OFF_VW, nullptr, nullptr,
                              g_h + OFF_VO, g_l + OFF_VO, 1.0f);
    }
}

// ====== merged: output projection (blocks 0..255) + avg_w (blocks 256..4351) =
__global__ __launch_bounds__(256, 2) void out_and_avg(
    const float* __restrict__ bias, float* __restrict__ Z, float* __restrict__ avgw)
{
    if (blockIdx.x < 256) {
        int m0 = (blockIdx.x >> 3) * 128, n0 = (blockIdx.x & 7) * 128;
        gemm_cpasync_body(m0, n0, OFF_AT, OFF_OW, bias, Z, nullptr, nullptr, 1.0f);
        return;
    }
    extern __shared__ __align__(16) unsigned char sm[];
    float* ms  = (float*)sm;
    float* ils = ms + H_;
    float* cf  = ils + H_;
    int li = blockIdx.x - 256;
    int s = li & (S_ - 1), b = li >> 11;
    int tid = threadIdx.x;
    if (tid < H_) {
        ms[tid]  = g_m [((size_t)b * H_ + tid) * S_ + s];
        ils[tid] = g_il[((size_t)b * H_ + tid) * S_ + s];
    }
    __syncthreads();
    const float invH = 1.0f / (float)H_;
    #pragma unroll
    for (int i = tid; i < H_ * 32; i += 256) {
        int h = i >> 5, tile = i & 31;
        float ml = g_ml[(((size_t)b * S_ + s) * H_ + h) * 32 + tile];
        cf[i] = __expf(ml - ms[h]) * ils[h] * invH;
    }
    __syncthreads();

    const int col = tid * 8;
    const int tile = col >> 6;
    float a[8] = {};
    #pragma unroll 4
    for (int h = 0; h < H_; h++) {
        uint4 pv = *(const uint4*)&g_P[((size_t)(b * H_ + h) * S_ + s) * S_ + col];
        float c = cf[h * 32 + tile];
        const __half2* hp = (const __half2*)&pv;
        #pragma unroll
        for (int q = 0; q < 4; q++) {
            float2 f = __half22float2(hp[q]);
            a[2*q]   += f.x * c;
            a[2*q+1] += f.y * c;
        }
    }
    float4 o0 = {a[0], a[1], a[2], a[3]};
    float4 o1 = {a[4], a[5], a[6], a[7]};
    *(float4*)&avgw[((size_t)b * S_ + s) * S_ + col]     = o0;
    *(float4*)&avgw[((size_t)b * S_ + s) * S_ + col + 4] = o1;
}

// ============ persistent fused flash attention (512 items off g_ctr[1]) ======
__global__ __launch_bounds__(256, 2) void attn_fused_mma(
    const float* __restrict__ td,
    const float* __restrict__ fa, const float* __restrict__ fb,
    const float* __restrict__ fc, const float* __restrict__ fd)
{
    extern __shared__ __align__(16) unsigned char smem[];
    const uint32_t QH = 0, QL = 16384, STG = 32768;
    float* tq_s = (float*)(smem + 98304);
    float* tt_s = (float*)(smem + 98816);
    int*   s_w  = (int*)(smem + 99328);
    const uint32_t sb = smem_u32(smem);

    const int tid = threadIdx.x, lane = tid & 31, wid = tid >> 5;
    const float fav = *fa, fbv = *fb, fcv = *fc, fdv = *fd;

    const __nv_bfloat16* Qh = g_h + OFF_QO; const __nv_bfloat16* Ql = g_l + OFF_QO;
    const __nv_bfloat16* Kh = g_h + OFF_KO; const __nv_bfloat16* Kl = g_l + OFF_KO;
    const __nv_bfloat16* Vh = g_h + OFF_VO; const __nv_bfloat16* Vl = g_l + OFF_VO;

    const int t8 = lane >> 3, l7 = lane & 7;
    const int knrb = ((t8 >> 1) << 3) + l7;
    const int vtrb = ((t8 & 1) << 3) + l7;

    for (;;) {
        __syncthreads();                 // previous item fully done (smem free)
        if (tid == 0) *s_w = atomicAdd(&g_ctr[1], 1);
        __syncthreads();
        const int w = *s_w;
        if (w >= 512) return;
        const int q0 = (w & 15) * 128, h = (w >> 4) & 15, b = w >> 8;
        const int qrow = (wid << 4) + ((t8 & 1) << 3) + l7;
        const int r0g = q0 + (wid << 4) + (lane >> 2);

        // ---- issue Q tile + KV tile 0 ----
        #pragma unroll
        for (int i = 0; i < 4; i++) {
            int gc = tid * 4 + i;
            int row = gc >> 3, c = gc & 7;
            size_t gi = ((size_t)(q0 + row) * B_ + b) * E_ + h * DH_ + c * 8;
            uint32_t d = sb + QH + (uint32_t)(row * 128 + ((c ^ (row & 7)) << 4));
            CP_ASYNC16(d, Qh + gi);
            CP_ASYNC16(d + (QL - QH), Ql + gi);
        }
        CP_COMMIT();

        int kvrow[2], kvc[2]; size_t kvbase[2];
        #pragma unroll
        for (int i = 0; i < 2; i++) {
            int gc = tid * 2 + i;
            kvrow[i] = gc >> 3; kvc[i] = gc & 7;
            kvbase[i] = ((size_t)kvrow[i] * B_ + b) * E_ + h * DH_ + kvc[i] * 8;
        }
        #define ISSUE_KV(t0, s) do {                                           \
            uint32_t stb = sb + STG + (uint32_t)(s) * 32768;                   \
            _Pragma("unroll")                                                  \
            for (int i = 0; i < 2; i++) {                                      \
                size_t gi = kvbase[i] + (size_t)(t0) * (B_ * E_);              \
                uint32_t d = stb + (uint32_t)(kvrow[i] * 128 + ((kvc[i] ^ (kvrow[i] & 7)) << 4)); \
                CP_ASYNC16(d,         Kh + gi);                                \
                CP_ASYNC16(d +  8192, Kl + gi);                                \
                CP_ASYNC16(d + 16384, Vh + gi);                                \
                CP_ASYNC16(d + 24576, Vl + gi);                                \
            }                                                                  \
            CP_COMMIT();                                                       \
        } while (0)

        ISSUE_KV(0, 0);
        if (tid < 128) tq_s[tid] = td[b * S_ + q0 + tid];
        else if (tid < 192) tt_s[tid - 128] = td[b * S_ + tid - 128];
        CP_WAIT0();
        __syncthreads();

        const float tqa = tq_s[(wid << 4) + (lane >> 2)];
        const float tqb = tq_s[(wid << 4) + (lane >> 2) + 8];

        float m0r = -1e30f, m1r = -1e30f, l0r = 0.f, l1r = 0.f;
        float o[8][4] = {};
        __half* Pbase = g_P + ((size_t)(b * H_ + h) * S_) * S_;

        for (int tt = 0; tt < 32; tt++) {
            const int t0 = tt * 64, s = tt & 1;
            if (tt + 1 < 32) {
                ISSUE_KV(t0 + 64, s ^ 1);
                if (tid < 64) tt_s[((tt + 1) & 1) * 64 + tid] = td[b * S_ + t0 + 64 + tid];
            }
            const uint32_t KB = sb + STG + (uint32_t)s * 32768;
            const float* ttp = tt_s + s * 64;

            float sc[8][4] = {};
            #pragma unroll
            for (int ks = 0; ks < 4; ks++) {
                int qc = 2 * ks + (t8 >> 1);
                uint32_t qa = sb + QH + qrow * 128 + ((qc ^ (qrow & 7)) << 4);
                uint32_t ah[4], al[4];
                ldsm4(ah, qa); ldsm4(al, qa + (QL - QH));
                #pragma unroll
                for (int np = 0; np < 4; np++) {
                    int nrow = (np << 4) + knrb;
                    int kc = 2 * ks + (t8 & 1);
                    uint32_t ka = KB + nrow * 128 + ((kc ^ (nrow & 7)) << 4);
                    uint32_t bh[4], bl[4];
                    ldsm4(bh, ka); ldsm4(bl, ka + 8192);
                    mma_bf16(sc[2*np],   ah, bh[0], bh[1]);
                    mma_bf16(sc[2*np],   ah, bl[0], bl[1]);
                    mma_bf16(sc[2*np],   al, bh[0], bh[1]);
                    mma_bf16(sc[2*np+1], ah, bh[2], bh[3]);
                    mma_bf16(sc[2*np+1], ah, bl[2], bl[3]);
                    mma_bf16(sc[2*np+1], al, bh[2], bh[3]);
                }
            }

            float mx0 = -1e30f, mx1 = -1e30f;
            #pragma unroll
            for (int j = 0; j < 8; j++) {
                float2 ttv = *(const float2*)&ttp[8 * j + 2 * (lane & 3)];
                float f00 = fcv * __fdividef(fbv, tqa - ttv.x + fav) + fdv;
                float f01 = fcv * __fdividef(fbv, tqa - ttv.y + fav) + fdv;
                float f10 = fcv * __fdividef(fbv, tqb - ttv.x + fav) + fdv;
                float f11 = fcv * __fdividef(fbv, tqb - ttv.y + fav) + fdv;
                sc[j][0] *= f00; sc[j][1] *= f01; sc[j][2] *= f10; sc[j][3] *= f11;
                mx0 = fmaxf(mx0, fmaxf(sc[j][0], sc[j][1]));
                mx1 = fmaxf(mx1, fmaxf(sc[j][2], sc[j][3]));
            }
            mx0 = fmaxf(mx0, __shfl_xor_sync(0xffffffffu, mx0, 1));
            mx0 = fmaxf(mx0, __shfl_xor_sync(0xffffffffu, mx0, 2));
            mx1 = fmaxf(mx1, __shfl_xor_sync(0xffffffffu, mx1, 1));
            mx1 = fmaxf(mx1, __shfl_xor_sync(0xffffffffu, mx1, 2));

            float mn0 = fmaxf(m0r, mx0), mn1 = fmaxf(m1r, mx1);
            float al0 = __expf(m0r - mn0), al1 = __expf(m1r - mn1);
            float ps0 = 0.f, ps1 = 0.f;
            #pragma unroll
            for (int j = 0; j < 8; j++) {
                sc[j][0] = __expf(sc[j][0] - mn0); sc[j][1] = __expf(sc[j][1] - mn0);
                sc[j][2] = __expf(sc[j][2] - mn1); sc[j][3] = __expf(sc[j][3] - mn1);
                ps0 += sc[j][0] + sc[j][1];
                ps1 += sc[j][2] + sc[j][3];
                int col = t0 + 8 * j + 2 * (lane & 3);
                *(__half2*)&Pbase[(size_t)r0g * S_ + col]       = __floats2half2_rn(sc[j][0], sc[j][1]);
                *(__half2*)&Pbase[(size_t)(r0g + 8) * S_ + col] = __floats2half2_rn(sc[j][2], sc[j][3]);
            }
            if ((lane & 3) == 0) {
                g_ml[(((size_t)b * S_ + r0g)     * H_ + h) * 32 + tt] = mn0;
                g_ml[(((size_t)b * S_ + r0g + 8) * H_ + h) * 32 + tt] = mn1;
            }
            ps0 += __shfl_xor_sync(0xffffffffu, ps0, 1); ps0 += __shfl_xor_sync(0xffffffffu, ps0, 2);
            ps1 += __shfl_xor_sync(0xffffffffu, ps1, 1); ps1 += __shfl_xor_sync(0xffffffffu, ps1, 2);
            l0r = l0r * al0 + ps0; l1r = l1r * al1 + ps1;
            m0r = mn0; m1r = mn1;
            #pragma unroll
            for (int j = 0; j < 8; j++) {
                o[j][0] *= al0; o[j][1] *= al0; o[j][2] *= al1; o[j][3] *= al1;
            }

            #pragma unroll
            for (int ks = 0; ks < 4; ks++) {
                uint32_t ah[4], alr[4];
                #pragma unroll
                for (int half = 0; half < 2; half++) {
                    int jt = 2 * ks + half;
                    uint32_t h0 = packbf2(sc[jt][0], sc[jt][1]);
                    uint32_t h1 = packbf2(sc[jt][2], sc[jt][3]);
                    float e00 = __uint_as_float(h0 << 16), e01 = __uint_as_float(h0 & 0xFFFF0000u);
                    float e10 = __uint_as_float(h1 << 16), e11 = __uint_as_float(h1 & 0xFFFF0000u);
                    ah [half*2]   = h0; ah [half*2+1] = h1;
                    alr[half*2]   = packbf2(sc[jt][0] - e00, sc[jt][1] - e01);
                    alr[half*2+1] = packbf2(sc[jt][2] - e10, sc[jt][3] - e11);
                }
                #pragma unroll
                for (int dp = 0; dp < 4; dp++) {
                    int trow = (ks << 4) + vtrb;
                    int dc = 2 * dp + (t8 >> 1);
                    uint32_t va = KB + 16384 + trow * 128 + ((dc ^ (trow & 7)) << 4);
                    uint32_t vh[4], vl[4];
                    ldsm4t(vh, va); ldsm4t(vl, va + 8192);
                    mma_bf16(o[2*dp],   ah,  vh[0], vh[1]);
                    mma_bf16(o[2*dp],   ah,  vl[0], vl[1]);
                    mma_bf16(o[2*dp],   alr, vh[0], vh[1]);
                    mma_bf16(o[2*dp+1], ah,  vh[2], vh[3]);
                    mma_bf16(o[2*dp+1], ah,  vl[2], vl[3]);
                    mma_bf16(o[2*dp+1], alr, vh[2], vh[3]);
                }
            }

            if (tt + 1 < 32) CP_WAIT0();
            __syncthreads();
        }
        #undef ISSUE_KV

        float il0 = 1.0f / l0r, il1 = 1.0f / l1r;
        #pragma unroll
        for (int j = 0; j < 8; j++) {
            int d = h * DH_ + 8 * j + 2 * (lane & 3);
            float p0 = o[j][0] * il0, p1 = o[j][1] * il0;
            float p2 = o[j][2] * il1, p3 = o[j][3] * il1;
            uint32_t h0 = packbf2(p0, p1), h1 = packbf2(p2, p3);
            float e00 = __uint_as_float(h0 << 16), e01 = __uint_as_float(h0 & 0xFFFF0000u);
            float e10 = __uint_as_float(h1 << 16), e11 = __uint_as_float(h1 & 0xFFFF0000u);
            uint32_t l0v = packbf2(p0 - e00, p1 - e01);
            uint32_t l1v = packbf2(p2 - e10, p3 - e11);
            size_t i0 = ((size_t)r0g * B_ + b) * E_ + d;
            size_t i1 = ((size_t)(r0g + 8) * B_ + b) * E_ + d;
            *(uint32_t*)&g_h[OFF_AT + i0] = h0; *(uint32_t*)&g_l[OFF_AT + i0] = l0v;
            *(uint32_t*)&g_h[OFF_AT + i1] = h1; *(uint32_t*)&g_l[OFF_AT + i1] = l1v;
        }
        if ((lane & 3) == 0) {
            size_t base = (size_t)(b * H_ + h) * S_;
            g_m [base + r0g]     = m0r; g_il[base + r0g]     = il0;
            g_m [base + r0g + 8] = m1r; g_il[base + r0g + 8] = il1;
        }
    }
}

// ---------------------------------------------------------------------------
extern "C" void kernel_launch(void* const* d_in, const int* in_sizes, int n_in,
                              void* d_out, int out_size)
{
    const float* query = (const float*)d_in[0];
    const float* key_t = (const float*)d_in[1];
    const float* value = (const float*)d_in[2];
    const float* td    = (const float*)d_in[3];
    const float* q_w   = (const float*)d_in[4];
    const float* k_w   = (const float*)d_in[5];
    const float* v_w   = (const float*)d_in[6];
    const float* out_w = (const float*)d_in[7];
    const float* out_b = (const float*)d_in[8];
    const float* fa    = (const float*)d_in[9];
    const float* fb    = (const float*)d_in[10];
    const float* fc    = (const float*)d_in[11];
    const float* fd    = (const float*)d_in[12];

    float* Z    = (float*)d_out;                        // [S,B,E]
    float* avgw = (float*)d_out + (size_t)S_ * B_ * E_; // [B,S,S]

    const int smem_attn = 99328 + 16;
    const int smem_gemm = 81920;
    cudaFuncSetAttribute(attn_fused_mma, cudaFuncAttributeMaxDynamicSharedMemorySize, smem_attn);
    cudaFuncSetAttribute(proj3_persist,  cudaFuncAttributeMaxDynamicSharedMemorySize, smem_gemm);
    cudaFuncSetAttribute(out_and_avg,    cudaFuncAttributeMaxDynamicSharedMemorySize, smem_gemm);

    const int SLOTS = 304;   // 152 SMs x 2 blocks/SM

    // all 7 fp32->bf16 hi/lo splits + counter reset in one launch
    const int total_chunks = 3 * (MR_ * E_ / 8) + 4 * (E_ * E_ / 8);   // 2097152
    split_all<<<total_chunks / 256, 256>>>(query, key_t, value, q_w, k_w, v_w, out_w);
    // Q,K,V projections: persistent blocks pulling 768 tiles dynamically
    proj3_persist<<<SLOTS, 256, smem_gemm>>>();
    // fused flash attention: persistent blocks pulling 512 items dynamically
    attn_fused_mma<<<SLOTS, 256, smem_attn>>>(td, fa, fb, fc, fd);
    // output projection + head-averaged weights, co-scheduled
    out_and_avg<<<256 + S_ * B_, 256, smem_gemm>>>(out_b, Z, avgw);
}

// round 16
// speedup vs baseline: 1.0104x; 1.0104x over previous
#include <cuda_runtime.h>
#include <cuda_bf16.h>
#include <cuda_fp16.h>
#include <cstdint>

static constexpr int S_  = 2048;
static constexpr int B_  = 2;
static constexpr int E_  = 1024;
static constexpr int H_  = 16;
static constexpr int DH_ = 64;
static constexpr int MR_ = S_ * B_;   // 4096

// ---------------- scratch (device globals: no allocations allowed) ----------
__device__ float g_m [B_ * H_ * S_];
__device__ float g_il[B_ * H_ * S_];
__device__ __half g_P[(size_t)B_ * H_ * S_ * S_];       // tile-local softmax numerators, 256 MB
__device__ float  g_ml[(size_t)B_ * S_ * H_ * 32];      // running max per (row, 64-t tile), 16 MB
// bf16 hi/lo pools (mirrored layout in g_h / g_l)
static constexpr uint32_t OFF_QI = 0,        OFF_KI = 4u<<20,  OFF_VI = 8u<<20,  OFF_AT = 12u<<20;
static constexpr uint32_t OFF_QW = 16u<<20,  OFF_KW = 17u<<20, OFF_VW = 18u<<20, OFF_OW = 19u<<20;
static constexpr uint32_t OFF_QO = 20u<<20,  OFF_KO = 24u<<20, OFF_VO = 28u<<20;
__device__ __nv_bfloat16 g_h[32u << 20];
__device__ __nv_bfloat16 g_l[32u << 20];

// ===================== mma.sync helpers (sm_80 baseline PTX) =================
__device__ __forceinline__ uint32_t smem_u32(const void* p) {
    uint32_t a;
    asm("{ .reg .u64 t; cvta.to.shared.u64 t, %1; cvt.u32.u64 %0, t; }" : "=r"(a) : "l"(p));
    return a;
}
__device__ __forceinline__ void ldsm4(uint32_t* r, uint32_t addr) {
    asm volatile("ldmatrix.sync.aligned.m8n8.x4.shared.b16 {%0,%1,%2,%3}, [%4];"
                 : "=r"(r[0]), "=r"(r[1]), "=r"(r[2]), "=r"(r[3]) : "r"(addr));
}
__device__ __forceinline__ void ldsm4t(uint32_t* r, uint32_t addr) {
    asm volatile("ldmatrix.sync.aligned.m8n8.x4.trans.shared.b16 {%0,%1,%2,%3}, [%4];"
                 : "=r"(r[0]), "=r"(r[1]), "=r"(r[2]), "=r"(r[3]) : "r"(addr));
}
__device__ __forceinline__ void mma_bf16(float* c, const uint32_t* a, uint32_t b0, uint32_t b1) {
    asm volatile("mma.sync.aligned.m16n8k16.row.col.f32.bf16.bf16.f32 "
                 "{%0,%1,%2,%3}, {%4,%5,%6,%7}, {%8,%9}, {%0,%1,%2,%3};"
                 : "+f"(c[0]), "+f"(c[1]), "+f"(c[2]), "+f"(c[3])
                 : "r"(a[0]), "r"(a[1]), "r"(a[2]), "r"(a[3]), "r"(b0), "r"(b1));
}
__device__ __forceinline__ uint32_t packbf2(float lo, float hi) {
    uint32_t r;
    asm("cvt.rn.bf16x2.f32 %0, %1, %2;" : "=r"(r) : "f"(hi), "f"(lo));
    return r;
}
// streaming (evict-first) store/load for write-once-read-once data
__device__ __forceinline__ void stg_cs_u32(void* p, uint32_t v) {
    asm volatile("st.global.cs.u32 [%0], %1;" :: "l"(p), "r"(v) : "memory");
}
__device__ __forceinline__ uint4 ldg_cs_u128(const void* p) {
    uint4 v;
    asm volatile("ld.global.nc.cs.v4.u32 {%0,%1,%2,%3}, [%4];"
                 : "=r"(v.x), "=r"(v.y), "=r"(v.z), "=r"(v.w) : "l"(p));
    return v;
}
#define CP_ASYNC16(dst, src) \
    asm volatile("cp.async.ca.shared.global [%0], [%1], 16;" :: "r"(dst), "l"(src) : "memory")
#define CP_COMMIT() asm volatile("cp.async.commit_group;" ::: "memory")
#define CP_WAIT0()  asm volatile("cp.async.wait_group 0;" ::: "memory")
#define CP_WAIT1()  asm volatile("cp.async.wait_group 1;" ::: "memory")

// ============== fused split: all 7 fp32 tensors -> bf16 hi/lo pools ==========
__global__ __launch_bounds__(256) void split_all(
    const float* __restrict__ q_in, const float* __restrict__ k_in,
    const float* __restrict__ v_in, const float* __restrict__ q_w,
    const float* __restrict__ k_w,  const float* __restrict__ v_w,
    const float* __restrict__ o_w)
{
    const int NI = MR_ * E_ / 8;      // 524288 chunks per input
    const int NW = E_ * E_ / 8;       // 131072 chunks per weight
    int i = blockIdx.x * blockDim.x + threadIdx.x;
    const float* src; uint32_t dst; int li;
    if      (i < NI)              { src = q_in; dst = OFF_QI; li = i; }
    else if (i < 2*NI)            { src = k_in; dst = OFF_KI; li = i - NI; }
    else if (i < 3*NI)            { src = v_in; dst = OFF_VI; li = i - 2*NI; }
    else if (i < 3*NI + NW)       { src = q_w;  dst = OFF_QW; li = i - 3*NI; }
    else if (i < 3*NI + 2*NW)     { src = k_w;  dst = OFF_KW; li = i - 3*NI - NW; }
    else if (i < 3*NI + 3*NW)     { src = v_w;  dst = OFF_VW; li = i - 3*NI - 2*NW; }
    else                          { src = o_w;  dst = OFF_OW; li = i - 3*NI - 3*NW; }

    float4 v0 = ((const float4*)src)[2*li], v1 = ((const float4*)src)[2*li+1];
    float x[8] = {v0.x, v0.y, v0.z, v0.w, v1.x, v1.y, v1.z, v1.w};
    uint4 h4, l4;
    uint32_t* hp = (uint32_t*)&h4; uint32_t* lp = (uint32_t*)&l4;
    #pragma unroll
    for (int p = 0; p < 4; p++) {
        uint32_t h = packbf2(x[2*p], x[2*p+1]);
        float xh = __uint_as_float(h << 16);
        float yh = __uint_as_float(h & 0xFFFF0000u);
        hp[p] = h;
        lp[p] = packbf2(x[2*p] - xh, x[2*p+1] - yh);
    }
    ((uint4*)(g_h + dst))[li] = h4;
    ((uint4*)(g_l + dst))[li] = l4;
}

// ===== bf16x3 GEMM tile body, cp.async 2-stage k-32 (R12-frozen schedule) ====
__device__ __forceinline__ void gemm_cpasync_body(
    int m0, int n0, uint32_t offA, uint32_t offW,
    const float* __restrict__ bias, float* __restrict__ C,
    __nv_bfloat16* __restrict__ Ch, __nv_bfloat16* __restrict__ Cl, float scale)
{
    extern __shared__ __align__(16) unsigned char sm[];
    const int tid = threadIdx.x, lane = tid & 31, wid = tid >> 5;
    const int wm = wid & 3, wn = wid >> 2;
    const uint32_t sb = smem_u32(sm);

    uint32_t offs[8], dofs[8];
    #pragma unroll
    for (int c = 0; c < 8; c++) {
        int g = c * 256 + tid;
        int part = g >> 10, idx = g & 1023, hl = idx >> 9, rc = idx & 511;
        int row = rc >> 2, ch = rc & 3;
        uint32_t o = (part ? offW : offA)
                   + (uint32_t)((part ? n0 : m0) + row) * E_ + ch * 8;
        offs[c] = o | (hl ? 0x80000000u : 0u);
        dofs[c] = (uint32_t)(part * 20480 + hl * 10240 + row * 80 + ch * 16);
    }

    #define ISSUE_STAGE(s, k0) do {                                            \
        uint32_t stb = sb + (s) * 40960;                                       \
        _Pragma("unroll")                                                      \
        for (int c = 0; c < 8; c++) {                                          \
            uint32_t o = offs[c];                                              \
            const __nv_bfloat16* base = (o & 0x80000000u) ? g_l : g_h;         \
            CP_ASYNC16(stb + dofs[c], base + (o & 0x7FFFFFFFu) + (k0));        \
        }                                                                      \
        CP_COMMIT();                                                           \
    } while (0)

    ISSUE_STAGE(0, 0);
    ISSUE_STAGE(1, 32);
    CP_WAIT1();
    __syncthreads();

    float acc[2][8][4] = {};
    const int lr = lane & 15, lkh = lane >> 4;

    for (int kb = 0; kb < 32; kb++) {
        int s = kb & 1;
        uint32_t Ab = sb + s * 40960;
        uint32_t Wb = Ab + 20480;
        #pragma unroll
        for (int ks = 0; ks < 2; ks++) {
            uint32_t aH[2][4], aL[2][4];
            #pragma unroll
            for (int i = 0; i < 2; i++) {
                uint32_t ad = Ab + (wm * 32 + i * 16 + lr) * 80 + ks * 32 + lkh * 16;
                ldsm4(aH[i], ad); ldsm4(aL[i], ad + 10240);
            }
            #pragma unroll
            for (int np = 0; np < 4; np++) {
                uint32_t wa = Wb + (wn * 64 + np * 16 + lr) * 80 + ks * 32 + lkh * 16;
                uint32_t wHf[4], wLf[4];
                ldsm4(wHf, wa); ldsm4(wLf, wa + 10240);
                #pragma unroll
                for (int i = 0; i < 2; i++)
                    #pragma unroll
                    for (int js = 0; js < 2; js++) {
                        int j = np * 2 + js;
                        mma_bf16(acc[i][j], aH[i], wHf[js], wHf[js + 2]);
                        mma_bf16(acc[i][j], aH[i], wLf[js], wLf[js + 2]);
                        mma_bf16(acc[i][j], aL[i], wHf[js], wHf[js + 2]);
                    }
            }
        }
        __syncthreads();
        if (kb + 2 < 32) {
            ISSUE_STAGE(s, (kb + 2) * 32);
            CP_WAIT1();
        } else {
            CP_WAIT0();
        }
        __syncthreads();
    }
    #undef ISSUE_STAGE

    #pragma unroll
    for (int i = 0; i < 2; i++) {
        int mrow = m0 + wm * 32 + i * 16 + (lane >> 2);
        #pragma unroll
        for (int j = 0; j < 8; j++) {
            int n = n0 + wn * 64 + j * 8 + (lane & 3) * 2;
            float c0 = acc[i][j][0] * scale, c1 = acc[i][j][1] * scale;
            float c2 = acc[i][j][2] * scale, c3 = acc[i][j][3] * scale;
            if (Ch) {
                uint32_t h0 = packbf2(c0, c1), h1 = packbf2(c2, c3);
                float e00 = __uint_as_float(h0 << 16), e01 = __uint_as_float(h0 & 0xFFFF0000u);
                float e10 = __uint_as_float(h1 << 16), e11 = __uint_as_float(h1 & 0xFFFF0000u);
                uint32_t l0 = packbf2(c0 - e00, c1 - e01);
                uint32_t l1 = packbf2(c2 - e10, c3 - e11);
                size_t i0 = (size_t)mrow * E_ + n, i1 = (size_t)(mrow + 8) * E_ + n;
                *(uint32_t*)&Ch[i0] = h0; *(uint32_t*)&Cl[i0] = l0;
                *(uint32_t*)&Ch[i1] = h1; *(uint32_t*)&Cl[i1] = l1;
            } else {
                float bx = 0.f, by = 0.f;
                if (bias) { float2 bv = *(const float2*)&bias[n]; bx = bv.x; by = bv.y; }
                *(float2*)&C[(size_t)mrow * E_ + n]       = make_float2(c0 + bx, c1 + by);
                *(float2*)&C[(size_t)(mrow + 8) * E_ + n] = make_float2(c2 + bx, c3 + by);
            }
        }
    }
}

__global__ __launch_bounds__(256, 2) void proj3_cp()
{
    int m0 = blockIdx.y * 128, n0 = blockIdx.x * 128;
    if (blockIdx.z == 0)
        gemm_cpasync_body(m0, n0, OFF_QI, OFF_QW, nullptr, nullptr,
                          g_h + OFF_QO, g_l + OFF_QO, 0.125f);
    else if (blockIdx.z == 1)
        gemm_cpasync_body(m0, n0, OFF_KI, OFF_KW, nullptr, nullptr,
                          g_h + OFF_KO, g_l + OFF_KO, 1.0f);
    else
        gemm_cpasync_body(m0, n0, OFF_VI, OFF_VW, nullptr, nullptr,
                          g_h + OFF_VO, g_l + OFF_VO, 1.0f);
}

// ====== merged: output projection (blocks 0..255) + avg_w (blocks 256..4351) =
__global__ __launch_bounds__(256, 2) void out_and_avg(
    const float* __restrict__ bias, float* __restrict__ Z, float* __restrict__ avgw)
{
    if (blockIdx.x < 256) {
        int m0 = (blockIdx.x >> 3) * 128, n0 = (blockIdx.x & 7) * 128;
        gemm_cpasync_body(m0, n0, OFF_AT, OFF_OW, bias, Z, nullptr, nullptr, 1.0f);
        return;
    }
    extern __shared__ __align__(16) unsigned char sm[];
    float* ms  = (float*)sm;
    float* ils = ms + H_;
    float* cf  = ils + H_;
    int li = blockIdx.x - 256;
    int s = li & (S_ - 1), b = li >> 11;
    int tid = threadIdx.x;
    if (tid < H_) {
        ms[tid]  = g_m [((size_t)b * H_ + tid) * S_ + s];
        ils[tid] = g_il[((size_t)b * H_ + tid) * S_ + s];
    }
    __syncthreads();
    const float invH = 1.0f / (float)H_;
    #pragma unroll
    for (int i = tid; i < H_ * 32; i += 256) {
        int h = i >> 5, tile = i & 31;
        float ml = g_ml[(((size_t)b * S_ + s) * H_ + h) * 32 + tile];
        cf[i] = __expf(ml - ms[h]) * ils[h] * invH;
    }
    __syncthreads();

    const int col = tid * 8;
    const int tile = col >> 6;
    float a[8] = {};
    #pragma unroll 4
    for (int h = 0; h < H_; h++) {
        uint4 pv = ldg_cs_u128(&g_P[((size_t)(b * H_ + h) * S_ + s) * S_ + col]);
        float c = cf[h * 32 + tile];
        const __half2* hp = (const __half2*)&pv;
        #pragma unroll
        for (int q = 0; q < 4; q++) {
            float2 f = __half22float2(hp[q]);
            a[2*q]   += f.x * c;
            a[2*q+1] += f.y * c;
        }
    }
    float4 o0 = {a[0], a[1], a[2], a[3]};
    float4 o1 = {a[4], a[5], a[6], a[7]};
    *(float4*)&avgw[((size_t)b * S_ + s) * S_ + col]     = o0;
    *(float4*)&avgw[((size_t)b * S_ + s) * S_ + col + 4] = o1;
}

// ============ fused flash attention: pool-native, cp.async double-buffered ===
__global__ __launch_bounds__(256, 2) void attn_fused_mma(
    const float* __restrict__ td,
    const float* __restrict__ fa, const float* __restrict__ fb,
    const float* __restrict__ fc, const float* __restrict__ fd)
{
    extern __shared__ __align__(16) unsigned char smem[];
    const uint32_t QH = 0, QL = 16384, STG = 32768;
    float* tq_s = (float*)(smem + 98304);
    float* tt_s = (float*)(smem + 98816);
    const uint32_t sb = smem_u32(smem);

    const int q0 = blockIdx.x * 128, h = blockIdx.y, b = blockIdx.z;
    const int tid = threadIdx.x, lane = tid & 31, wid = tid >> 5;
    const float fav = *fa, fbv = *fb, fcv = *fc, fdv = *fd;

    const __nv_bfloat16* Qh = g_h + OFF_QO; const __nv_bfloat16* Ql = g_l + OFF_QO;
    const __nv_bfloat16* Kh = g_h + OFF_KO; const __nv_bfloat16* Kl = g_l + OFF_KO;
    const __nv_bfloat16* Vh = g_h + OFF_VO; const __nv_bfloat16* Vl = g_l + OFF_VO;

    #pragma unroll
    for (int i = 0; i < 4; i++) {
        int gc = tid * 4 + i;
        int row = gc >> 3, c = gc & 7;
        size_t gi = ((size_t)(q0 + row) * B_ + b) * E_ + h * DH_ + c * 8;
        uint32_t d = sb + QH + (uint32_t)(row * 128 + ((c ^ (row & 7)) << 4));
        CP_ASYNC16(d, Qh + gi);
        CP_ASYNC16(d + (QL - QH), Ql + gi);
    }
    CP_COMMIT();

    int kvrow[2], kvc[2]; size_t kvbase[2];
    #pragma unroll
    for (int i = 0; i < 2; i++) {
        int gc = tid * 2 + i;
        kvrow[i] = gc >> 3; kvc[i] = gc & 7;
        kvbase[i] = ((size_t)kvrow[i] * B_ + b) * E_ + h * DH_ + kvc[i] * 8;
    }
    #define ISSUE_KV(t0, s) do {                                               \
        uint32_t stb = sb + STG + (uint32_t)(s) * 32768;                       \
        _Pragma("unroll")                                                      \
        for (int i = 0; i < 2; i++) {                                          \
            size_t gi = kvbase[i] + (size_t)(t0) * (B_ * E_);                  \
            uint32_t d = stb + (uint32_t)(kvrow[i] * 128 + ((kvc[i] ^ (kvrow[i] & 7)) << 4)); \
            CP_ASYNC16(d,         Kh + gi);                                    \
            CP_ASYNC16(d +  8192, Kl + gi);                                    \
            CP_ASYNC16(d + 16384, Vh + gi);                                    \
            CP_ASYNC16(d + 24576, Vl + gi);                                    \
        }                                                                      \
        CP_COMMIT();                                                           \
    } while (0)

    ISSUE_KV(0, 0);
    if (tid < 128) tq_s[tid] = td[b * S_ + q0 + tid];
    else if (tid < 192) tt_s[tid - 128] = td[b * S_ + tid - 128];
    CP_WAIT0();
    __syncthreads();

    const float tqa = tq_s[(wid << 4) + (lane >> 2)];
    const float tqb = tq_s[(wid << 4) + (lane >> 2) + 8];

    const int t8 = lane >> 3, l7 = lane & 7;
    const int qrow = (wid << 4) + ((t8 & 1) << 3) + l7;
    const int knrb = ((t8 >> 1) << 3) + l7;
    const int vtrb = ((t8 & 1) << 3) + l7;
    const int r0g = q0 + (wid << 4) + (lane >> 2);

    float m0r = -1e30f, m1r = -1e30f, l0r = 0.f, l1r = 0.f;
    float o[8][4] = {};
    __half* Pbase = g_P + ((size_t)(b * H_ + h) * S_) * S_;

    for (int tt = 0; tt < 32; tt++) {
        const int t0 = tt * 64, s = tt & 1;
        if (tt + 1 < 32) {
            ISSUE_KV(t0 + 64, s ^ 1);
            if (tid < 64) tt_s[((tt + 1) & 1) * 64 + tid] = td[b * S_ + t0 + 64 + tid];
        }
        const uint32_t KB = sb + STG + (uint32_t)s * 32768;
        const float* ttp = tt_s + s * 64;

        float sc[8][4] = {};
        #pragma unroll
        for (int ks = 0; ks < 4; ks++) {
            int qc = 2 * ks + (t8 >> 1);
            uint32_t qa = sb + QH + qrow * 128 + ((qc ^ (qrow & 7)) << 4);
            uint32_t ah[4], al[4];
            ldsm4(ah, qa); ldsm4(al, qa + (QL - QH));
            #pragma unroll
            for (int np = 0; np < 4; np++) {
                int nrow = (np << 4) + knrb;
                int kc = 2 * ks + (t8 & 1);
                uint32_t ka = KB + nrow * 128 + ((kc ^ (nrow & 7)) << 4);
                uint32_t bh[4], bl[4];
                ldsm4(bh, ka); ldsm4(bl, ka + 8192);
                mma_bf16(sc[2*np],   ah, bh[0], bh[1]);
                mma_bf16(sc[2*np],   ah, bl[0], bl[1]);
                mma_bf16(sc[2*np],   al, bh[0], bh[1]);
                mma_bf16(sc[2*np+1], ah, bh[2], bh[3]);
                mma_bf16(sc[2*np+1], ah, bl[2], bl[3]);
                mma_bf16(sc[2*np+1], al, bh[2], bh[3]);
            }
        }

        float mx0 = -1e30f, mx1 = -1e30f;
        #pragma unroll
        for (int j = 0; j < 8; j++) {
            float2 ttv = *(const float2*)&ttp[8 * j + 2 * (lane & 3)];
            float f00 = fcv * __fdividef(fbv, tqa - ttv.x + fav) + fdv;
            float f01 = fcv * __fdividef(fbv, tqa - ttv.y + fav) + fdv;
            float f10 = fcv * __fdividef(fbv, tqb - ttv.x + fav) + fdv;
            float f11 = fcv * __fdividef(fbv, tqb - ttv.y + fav) + fdv;
            sc[j][0] *= f00; sc[j][1] *= f01; sc[j][2] *= f10; sc[j][3] *= f11;
            mx0 = fmaxf(mx0, fmaxf(sc[j][0], sc[j][1]));
            mx1 = fmaxf(mx1, fmaxf(sc[j][2], sc[j][3]));
        }
        mx0 = fmaxf(mx0, __shfl_xor_sync(0xffffffffu, mx0, 1));
        mx0 = fmaxf(mx0, __shfl_xor_sync(0xffffffffu, mx0, 2));
        mx1 = fmaxf(mx1, __shfl_xor_sync(0xffffffffu, mx1, 1));
        mx1 = fmaxf(mx1, __shfl_xor_sync(0xffffffffu, mx1, 2));

        float mn0 = fmaxf(m0r, mx0), mn1 = fmaxf(m1r, mx1);
        float al0 = __expf(m0r - mn0), al1 = __expf(m1r - mn1);
        float ps0 = 0.f, ps1 = 0.f;
        #pragma unroll
        for (int j = 0; j < 8; j++) {
            sc[j][0] = __expf(sc[j][0] - mn0); sc[j][1] = __expf(sc[j][1] - mn0);
            sc[j][2] = __expf(sc[j][2] - mn1); sc[j][3] = __expf(sc[j][3] - mn1);
            ps0 += sc[j][0] + sc[j][1];
            ps1 += sc[j][2] + sc[j][3];
            int col = t0 + 8 * j + 2 * (lane & 3);
            __half2 p01 = __floats2half2_rn(sc[j][0], sc[j][1]);
            __half2 p23 = __floats2half2_rn(sc[j][2], sc[j][3]);
            stg_cs_u32(&Pbase[(size_t)r0g * S_ + col],       *(uint32_t*)&p01);
            stg_cs_u32(&Pbase[(size_t)(r0g + 8) * S_ + col], *(uint32_t*)&p23);
        }
        if ((lane & 3) == 0) {
            stg_cs_u32(&g_ml[(((size_t)b * S_ + r0g)     * H_ + h) * 32 + tt], __float_as_uint(mn0));
            stg_cs_u32(&g_ml[(((size_t)b * S_ + r0g + 8) * H_ + h) * 32 + tt], __float_as_uint(mn1));
        }
        ps0 += __shfl_xor_sync(0xffffffffu, ps0, 1); ps0 += __shfl_xor_sync(0xffffffffu, ps0, 2);
        ps1 += __shfl_xor_sync(0xffffffffu, ps1, 1); ps1 += __shfl_xor_sync(0xffffffffu, ps1, 2);
        l0r = l0r * al0 + ps0; l1r = l1r * al1 + ps1;
        m0r = mn0; m1r = mn1;
        #pragma unroll
        for (int j = 0; j < 8; j++) {
            o[j][0] *= al0; o[j][1] *= al0; o[j][2] *= al1; o[j][3] *= al1;
        }

        #pragma unroll
        for (int ks = 0; ks < 4; ks++) {
            uint32_t ah[4], alr[4];
            #pragma unroll
            for (int half = 0; half < 2; half++) {
                int jt = 2 * ks + half;
                uint32_t h0 = packbf2(sc[jt][0], sc[jt][1]);
                uint32_t h1 = packbf2(sc[jt][2], sc[jt][3]);
                float e00 = __uint_as_float(h0 << 16), e01 = __uint_as_float(h0 & 0xFFFF0000u);
                float e10 = __uint_as_float(h1 << 16), e11 = __uint_as_float(h1 & 0xFFFF0000u);
                ah [half*2]   = h0; ah [half*2+1] = h1;
                alr[half*2]   = packbf2(sc[jt][0] - e00, sc[jt][1] - e01);
                alr[half*2+1] = packbf2(sc[jt][2] - e10, sc[jt][3] - e11);
            }
            #pragma unroll
            for (int dp = 0; dp < 4; dp++) {
                int trow = (ks << 4) + vtrb;
                int dc = 2 * dp + (t8 >> 1);
                uint32_t va = KB + 16384 + trow * 128 + ((dc ^ (trow & 7)) << 4);
                uint32_t vh[4], vl[4];
                ldsm4t(vh, va); ldsm4t(vl, va + 8192);
                mma_bf16(o[2*dp],   ah,  vh[0], vh[1]);
                mma_bf16(o[2*dp],   ah,  vl[0], vl[1]);
                mma_bf16(o[2*dp],   alr, vh[0], vh[1]);
                mma_bf16(o[2*dp+1], ah,  vh[2], vh[3]);
                mma_bf16(o[2*dp+1], ah,  vl[2], vl[3]);
                mma_bf16(o[2*dp+1], alr, vh[2], vh[3]);
            }
        }

        if (tt + 1 < 32) CP_WAIT0();
        __syncthreads();
    }
    #undef ISSUE_KV

    float il0 = 1.0f / l0r, il1 = 1.0f / l1r;
    #pragma unroll
    for (int j = 0; j < 8; j++) {
        int d = h * DH_ + 8 * j + 2 * (lane & 3);
        float p0 = o[j][0] * il0, p1 = o[j][1] * il0;
        float p2 = o[j][2] * il1, p3 = o[j][3] * il1;
        uint32_t h0 = packbf2(p0, p1), h1 = packbf2(p2, p3);
        float e00 = __uint_as_float(h0 << 16), e01 = __uint_as_float(h0 & 0xFFFF0000u);
        float e10 = __uint_as_float(h1 << 16), e11 = __uint_as_float(h1 & 0xFFFF0000u);
        uint32_t l0v = packbf2(p0 - e00, p1 - e01);
        uint32_t l1v = packbf2(p2 - e10, p3 - e11);
        size_t i0 = ((size_t)r0g * B_ + b) * E_ + d;
        size_t i1 = ((size_t)(r0g + 8) * B_ + b) * E_ + d;
        *(uint32_t*)&g_h[OFF_AT + i0] = h0; *(uint32_t*)&g_l[OFF_AT + i0] = l0v;
        *(uint32_t*)&g_h[OFF_AT + i1] = h1; *(uint32_t*)&g_l[OFF_AT + i1] = l1v;
    }
    if ((lane & 3) == 0) {
        size_t base = (size_t)(b * H_ + h) * S_;
        g_m [base + r0g]     = m0r; g_il[base + r0g]     = il0;
        g_m [base + r0g + 8] = m1r; g_il[base + r0g + 8] = il1;
    }
}

// ---------------------------------------------------------------------------
extern "C" void kernel_launch(void* const* d_in, const int* in_sizes, int n_in,
                              void* d_out, int out_size)
{
    const float* query = (const float*)d_in[0];
    const float* key_t = (const float*)d_in[1];
    const float* value = (const float*)d_in[2];
    const float* td    = (const float*)d_in[3];
    const float* q_w   = (const float*)d_in[4];
    const float* k_w   = (const float*)d_in[5];
    const float* v_w   = (const float*)d_in[6];
    const float* out_w = (const float*)d_in[7];
    const float* out_b = (const float*)d_in[8];
    const float* fa    = (const float*)d_in[9];
    const float* fb    = (const float*)d_in[10];
    const float* fc    = (const float*)d_in[11];
    const float* fd    = (const float*)d_in[12];

    float* Z    = (float*)d_out;                        // [S,B,E]
    float* avgw = (float*)d_out + (size_t)S_ * B_ * E_; // [B,S,S]

    const int smem_attn = 99328;
    const int smem_gemm = 81920;
    cudaFuncSetAttribute(attn_fused_mma, cudaFuncAttributeMaxDynamicSharedMemorySize, smem_attn);
    cudaFuncSetAttribute(proj3_cp,    cudaFuncAttributeMaxDynamicSharedMemorySize, smem_gemm);
    cudaFuncSetAttribute(out_and_avg, cudaFuncAttributeMaxDynamicSharedMemorySize, smem_gemm);

    // all 7 fp32->bf16 hi/lo splits in one launch
    const int total_chunks = 3 * (MR_ * E_ / 8) + 4 * (E_ * E_ / 8);   // 2097152
    split_all<<<total_chunks / 256, 256>>>(query, key_t, value, q_w, k_w, v_w, out_w);
    // Q,K,V projections -> bf16 hi/lo pools (R12-frozen schedule, 2 blocks/SM)
    proj3_cp<<<dim3(E_ / 128, MR_ / 128, 3), 256, smem_gemm>>>();
    // fused flash attention (pool-native, double-buffered K/V, streaming P)
    attn_fused_mma<<<dim3(S_ / 128, H_, B_), 256, smem_attn>>>(td, fa, fb, fc, fd);
    // output projection + head-averaged weights, co-scheduled in one launch
    out_and_avg<<<256 + S_ * B_, 256, smem_gemm>>>(out_b, Z, avgw);
}

// round 17
// speedup vs baseline: 1.0315x; 1.0209x over previous
#include <cuda_runtime.h>
#include <cuda_bf16.h>
#include <cuda_fp16.h>
#include <cstdint>

static constexpr int S_  = 2048;
static constexpr int B_  = 2;
static constexpr int E_  = 1024;
static constexpr int H_  = 16;
static constexpr int DH_ = 64;
static constexpr int MR_ = S_ * B_;   // 4096

// ---------------- scratch (device globals: no allocations allowed) ----------
__device__ float g_m [B_ * H_ * S_];
__device__ float g_il[B_ * H_ * S_];
__device__ __half g_P[(size_t)B_ * H_ * S_ * S_];       // tile-local softmax numerators, 256 MB
__device__ float  g_ml[(size_t)B_ * S_ * H_ * 32];      // running max per (row, 64-t tile), 16 MB
// bf16 hi/lo pools (mirrored layout in g_h / g_l)
static constexpr uint32_t OFF_QI = 0,        OFF_KI = 4u<<20,  OFF_VI = 8u<<20,  OFF_AT = 12u<<20;
static constexpr uint32_t OFF_QW = 16u<<20,  OFF_KW = 17u<<20, OFF_VW = 18u<<20, OFF_OW = 19u<<20;
static constexpr uint32_t OFF_QO = 20u<<20,  OFF_KO = 24u<<20, OFF_VO = 28u<<20;
__device__ __nv_bfloat16 g_h[32u << 20];
__device__ __nv_bfloat16 g_l[32u << 20];

// ===================== mma.sync helpers (sm_80 baseline PTX) =================
__device__ __forceinline__ uint32_t smem_u32(const void* p) {
    uint32_t a;
    asm("{ .reg .u64 t; cvta.to.shared.u64 t, %1; cvt.u32.u64 %0, t; }" : "=r"(a) : "l"(p));
    return a;
}
__device__ __forceinline__ void ldsm4(uint32_t* r, uint32_t addr) {
    asm volatile("ldmatrix.sync.aligned.m8n8.x4.shared.b16 {%0,%1,%2,%3}, [%4];"
                 : "=r"(r[0]), "=r"(r[1]), "=r"(r[2]), "=r"(r[3]) : "r"(addr));
}
__device__ __forceinline__ void ldsm4t(uint32_t* r, uint32_t addr) {
    asm volatile("ldmatrix.sync.aligned.m8n8.x4.trans.shared.b16 {%0,%1,%2,%3}, [%4];"
                 : "=r"(r[0]), "=r"(r[1]), "=r"(r[2]), "=r"(r[3]) : "r"(addr));
}
__device__ __forceinline__ void mma_bf16(float* c, const uint32_t* a, uint32_t b0, uint32_t b1) {
    asm volatile("mma.sync.aligned.m16n8k16.row.col.f32.bf16.bf16.f32 "
                 "{%0,%1,%2,%3}, {%4,%5,%6,%7}, {%8,%9}, {%0,%1,%2,%3};"
                 : "+f"(c[0]), "+f"(c[1]), "+f"(c[2]), "+f"(c[3])
                 : "r"(a[0]), "r"(a[1]), "r"(a[2]), "r"(a[3]), "r"(b0), "r"(b1));
}
__device__ __forceinline__ uint32_t packbf2(float lo, float hi) {
    uint32_t r;
    asm("cvt.rn.bf16x2.f32 %0, %1, %2;" : "=r"(r) : "f"(hi), "f"(lo));
    return r;
}
// streaming (evict-first) store/load for write-once-read-once data
__device__ __forceinline__ void stg_cs_u32(void* p, uint32_t v) {
    asm volatile("st.global.cs.u32 [%0], %1;" :: "l"(p), "r"(v) : "memory");
}
__device__ __forceinline__ uint4 ldg_cs_u128(const void* p) {
    uint4 v;
    asm volatile("ld.global.nc.cs.v4.u32 {%0,%1,%2,%3}, [%4];"
                 : "=r"(v.x), "=r"(v.y), "=r"(v.z), "=r"(v.w) : "l"(p));
    return v;
}
#define CP_ASYNC16(dst, src) \
    asm volatile("cp.async.ca.shared.global [%0], [%1], 16;" :: "r"(dst), "l"(src) : "memory")
#define CP_COMMIT() asm volatile("cp.async.commit_group;" ::: "memory")
#define CP_WAIT0()  asm volatile("cp.async.wait_group 0;" ::: "memory")
#define CP_WAIT1()  asm volatile("cp.async.wait_group 1;" ::: "memory")

// ============== fused split: all 7 fp32 tensors -> bf16 hi/lo pools ==========
__global__ __launch_bounds__(256) void split_all(
    const float* __restrict__ q_in, const float* __restrict__ k_in,
    const float* __restrict__ v_in, const float* __restrict__ q_w,
    const float* __restrict__ k_w,  const float* __restrict__ v_w,
    const float* __restrict__ o_w)
{
    const int NI = MR_ * E_ / 8;      // 524288 chunks per input
    const int NW = E_ * E_ / 8;       // 131072 chunks per weight
    int i = blockIdx.x * blockDim.x + threadIdx.x;
    const float* src; uint32_t dst; int li;
    if      (i < NI)              { src = q_in; dst = OFF_QI; li = i; }
    else if (i < 2*NI)            { src = k_in; dst = OFF_KI; li = i - NI; }
    else if (i < 3*NI)            { src = v_in; dst = OFF_VI; li = i - 2*NI; }
    else if (i < 3*NI + NW)       { src = q_w;  dst = OFF_QW; li = i - 3*NI; }
    else if (i < 3*NI + 2*NW)     { src = k_w;  dst = OFF_KW; li = i - 3*NI - NW; }
    else if (i < 3*NI + 3*NW)     { src = v_w;  dst = OFF_VW; li = i - 3*NI - 2*NW; }
    else                          { src = o_w;  dst = OFF_OW; li = i - 3*NI - 3*NW; }

    float4 v0 = ((const float4*)src)[2*li], v1 = ((const float4*)src)[2*li+1];
    float x[8] = {v0.x, v0.y, v0.z, v0.w, v1.x, v1.y, v1.z, v1.w};
    uint4 h4, l4;
    uint32_t* hp = (uint32_t*)&h4; uint32_t* lp = (uint32_t*)&l4;
    #pragma unroll
    for (int p = 0; p < 4; p++) {
        uint32_t h = packbf2(x[2*p], x[2*p+1]);
        float xh = __uint_as_float(h << 16);
        float yh = __uint_as_float(h & 0xFFFF0000u);
        hp[p] = h;
        lp[p] = packbf2(x[2*p] - xh, x[2*p+1] - yh);
    }
    ((uint4*)(g_h + dst))[li] = h4;
    ((uint4*)(g_l + dst))[li] = l4;
}

// ===== bf16x3 GEMM tile body, cp.async 2-stage k-32 (R12-frozen schedule) ====
__device__ __forceinline__ void gemm_cpasync_body(
    int m0, int n0, uint32_t offA, uint32_t offW,
    const float* __restrict__ bias, float* __restrict__ C,
    __nv_bfloat16* __restrict__ Ch, __nv_bfloat16* __restrict__ Cl, float scale)
{
    extern __shared__ __align__(16) unsigned char sm[];
    const int tid = threadIdx.x, lane = tid & 31, wid = tid >> 5;
    const int wm = wid & 3, wn = wid >> 2;
    const uint32_t sb = smem_u32(sm);

    uint32_t offs[8], dofs[8];
    #pragma unroll
    for (int c = 0; c < 8; c++) {
        int g = c * 256 + tid;
        int part = g >> 10, idx = g & 1023, hl = idx >> 9, rc = idx & 511;
        int row = rc >> 2, ch = rc & 3;
        uint32_t o = (part ? offW : offA)
                   + (uint32_t)((part ? n0 : m0) + row) * E_ + ch * 8;
        offs[c] = o | (hl ? 0x80000000u : 0u);
        dofs[c] = (uint32_t)(part * 20480 + hl * 10240 + row * 80 + ch * 16);
    }

    #define ISSUE_STAGE(s, k0) do {                                            \
        uint32_t stb = sb + (s) * 40960;                                       \
        _Pragma("unroll")                                                      \
        for (int c = 0; c < 8; c++) {                                          \
            uint32_t o = offs[c];                                              \
            const __nv_bfloat16* base = (o & 0x80000000u) ? g_l : g_h;         \
            CP_ASYNC16(stb + dofs[c], base + (o & 0x7FFFFFFFu) + (k0));        \
        }                                                                      \
        CP_COMMIT();                                                           \
    } while (0)

    ISSUE_STAGE(0, 0);
    ISSUE_STAGE(1, 32);
    CP_WAIT1();
    __syncthreads();

    float acc[2][8][4] = {};
    const int lr = lane & 15, lkh = lane >> 4;

    for (int kb = 0; kb < 32; kb++) {
        int s = kb & 1;
        uint32_t Ab = sb + s * 40960;
        uint32_t Wb = Ab + 20480;
        #pragma unroll
        for (int ks = 0; ks < 2; ks++) {
            uint32_t aH[2][4], aL[2][4];
            #pragma unroll
            for (int i = 0; i < 2; i++) {
                uint32_t ad = Ab + (wm * 32 + i * 16 + lr) * 80 + ks * 32 + lkh * 16;
                ldsm4(aH[i], ad); ldsm4(aL[i], ad + 10240);
            }
            #pragma unroll
            for (int np = 0; np < 4; np++) {
                uint32_t wa = Wb + (wn * 64 + np * 16 + lr) * 80 + ks * 32 + lkh * 16;
                uint32_t wHf[4], wLf[4];
                ldsm4(wHf, wa); ldsm4(wLf, wa + 10240);
                #pragma unroll
                for (int i = 0; i < 2; i++)
                    #pragma unroll
                    for (int js = 0; js < 2; js++) {
                        int j = np * 2 + js;
                        mma_bf16(acc[i][j], aH[i], wHf[js], wHf[js + 2]);
                        mma_bf16(acc[i][j], aH[i], wLf[js], wLf[js + 2]);
                        mma_bf16(acc[i][j], aL[i], wHf[js], wHf[js + 2]);
                    }
            }
        }
        __syncthreads();
        if (kb + 2 < 32) {
            ISSUE_STAGE(s, (kb + 2) * 32);
            CP_WAIT1();
        } else {
            CP_WAIT0();
        }
        __syncthreads();
    }
    #undef ISSUE_STAGE

    #pragma unroll
    for (int i = 0; i < 2; i++) {
        int mrow = m0 + wm * 32 + i * 16 + (lane >> 2);
        #pragma unroll
        for (int j = 0; j < 8; j++) {
            int n = n0 + wn * 64 + j * 8 + (lane & 3) * 2;
            float c0 = acc[i][j][0] * scale, c1 = acc[i][j][1] * scale;
            float c2 = acc[i][j][2] * scale, c3 = acc[i][j][3] * scale;
            if (Ch) {
                uint32_t h0 = packbf2(c0, c1), h1 = packbf2(c2, c3);
                float e00 = __uint_as_float(h0 << 16), e01 = __uint_as_float(h0 & 0xFFFF0000u);
                float e10 = __uint_as_float(h1 << 16), e11 = __uint_as_float(h1 & 0xFFFF0000u);
                uint32_t l0 = packbf2(c0 - e00, c1 - e01);
                uint32_t l1 = packbf2(c2 - e10, c3 - e11);
                size_t i0 = (size_t)mrow * E_ + n, i1 = (size_t)(mrow + 8) * E_ + n;
                *(uint32_t*)&Ch[i0] = h0; *(uint32_t*)&Cl[i0] = l0;
                *(uint32_t*)&Ch[i1] = h1; *(uint32_t*)&Cl[i1] = l1;
            } else {
                float bx = 0.f, by = 0.f;
                if (bias) { float2 bv = *(const float2*)&bias[n]; bx = bv.x; by = bv.y; }
                *(float2*)&C[(size_t)mrow * E_ + n]       = make_float2(c0 + bx, c1 + by);
                *(float2*)&C[(size_t)(mrow + 8) * E_ + n] = make_float2(c2 + bx, c3 + by);
            }
        }
    }
}

__global__ __launch_bounds__(256, 2) void proj3_cp()
{
    int m0 = blockIdx.y * 128, n0 = blockIdx.x * 128;
    if (blockIdx.z == 0)
        gemm_cpasync_body(m0, n0, OFF_QI, OFF_QW, nullptr, nullptr,
                          g_h + OFF_QO, g_l + OFF_QO, 0.125f);
    else if (blockIdx.z == 1)
        gemm_cpasync_body(m0, n0, OFF_KI, OFF_KW, nullptr, nullptr,
                          g_h + OFF_KO, g_l + OFF_KO, 1.0f);
    else
        gemm_cpasync_body(m0, n0, OFF_VI, OFF_VW, nullptr, nullptr,
                          g_h + OFF_VO, g_l + OFF_VO, 1.0f);
}

// ====== merged: output projection (blocks 0..255) + avg_w (blocks 256..2303) =
// avg blocks handle TWO s-rows each: doubles per-thread MLP to hide DRAM
// latency at the merged kernel's 2-blocks/SM occupancy cap.
__global__ __launch_bounds__(256, 2) void out_and_avg(
    const float* __restrict__ bias, float* __restrict__ Z, float* __restrict__ avgw)
{
    if (blockIdx.x < 256) {
        int m0 = (blockIdx.x >> 3) * 128, n0 = (blockIdx.x & 7) * 128;
        gemm_cpasync_body(m0, n0, OFF_AT, OFF_OW, bias, Z, nullptr, nullptr, 1.0f);
        return;
    }
    extern __shared__ __align__(16) unsigned char sm[];
    float* ms  = (float*)sm;             // 2 x 16
    float* ils = ms + 2 * H_;            // 2 x 16
    float* cf  = ils + 2 * H_;           // 2 x 512
    int li = blockIdx.x - 256;           // 0..2047
    int s0 = (li & 1023) * 2, b = li >> 10;
    int tid = threadIdx.x;
    if (tid < 2 * H_) {
        int r = tid >> 4, hh = tid & 15;
        ms [tid] = g_m [((size_t)b * H_ + hh) * S_ + s0 + r];
        ils[tid] = g_il[((size_t)b * H_ + hh) * S_ + s0 + r];
    }
    __syncthreads();
    const float invH = 1.0f / (float)H_;
    #pragma unroll
    for (int i = tid; i < 2 * H_ * 32; i += 256) {
        int r = i >> 9, rem = i & 511, h = rem >> 5, tile = rem & 31;
        float ml = g_ml[(((size_t)b * S_ + s0 + r) * H_ + h) * 32 + tile];
        cf[i] = __expf(ml - ms[r * H_ + h]) * ils[r * H_ + h] * invH;
    }
    __syncthreads();

    const int col = tid * 8;
    const int tile = col >> 6;
    float a0[8] = {}, a1[8] = {};
    #pragma unroll 4
    for (int h = 0; h < H_; h++) {
        const __half* rowb = &g_P[((size_t)(b * H_ + h) * S_ + s0) * S_ + col];
        uint4 pv0 = ldg_cs_u128(rowb);
        uint4 pv1 = ldg_cs_u128(rowb + S_);
        float c0 = cf[h * 32 + tile];
        float c1 = cf[512 + h * 32 + tile];
        const __half2* hp0 = (const __half2*)&pv0;
        const __half2* hp1 = (const __half2*)&pv1;
        #pragma unroll
        for (int q = 0; q < 4; q++) {
            float2 f0 = __half22float2(hp0[q]);
            float2 f1 = __half22float2(hp1[q]);
            a0[2*q]   += f0.x * c0; a0[2*q+1] += f0.y * c0;
            a1[2*q]   += f1.x * c1; a1[2*q+1] += f1.y * c1;
        }
    }
    float4 o00 = {a0[0], a0[1], a0[2], a0[3]};
    float4 o01 = {a0[4], a0[5], a0[6], a0[7]};
    float4 o10 = {a1[0], a1[1], a1[2], a1[3]};
    float4 o11 = {a1[4], a1[5], a1[6], a1[7]};
    float* out0 = &avgw[((size_t)b * S_ + s0) * S_ + col];
    *(float4*)out0        = o00;
    *(float4*)(out0 + 4)  = o01;
    *(float4*)(out0 + S_)     = o10;
    *(float4*)(out0 + S_ + 4) = o11;
}

// ============ fused flash attention: pool-native, cp.async double-buffered ===
__global__ __launch_bounds__(256, 2) void attn_fused_mma(
    const float* __restrict__ td,
    const float* __restrict__ fa, const float* __restrict__ fb,
    const float* __restrict__ fc, const float* __restrict__ fd)
{
    extern __shared__ __align__(16) unsigned char smem[];
    const uint32_t QH = 0, QL = 16384, STG = 32768;
    float* tq_s = (float*)(smem + 98304);
    float* tt_s = (float*)(smem + 98816);
    const uint32_t sb = smem_u32(smem);

    const int q0 = blockIdx.x * 128, h = blockIdx.y, b = blockIdx.z;
    const int tid = threadIdx.x, lane = tid & 31, wid = tid >> 5;
    const float fav = *fa, fbv = *fb, fcv = *fc, fdv = *fd;

    const __nv_bfloat16* Qh = g_h + OFF_QO; const __nv_bfloat16* Ql = g_l + OFF_QO;
    const __nv_bfloat16* Kh = g_h + OFF_KO; const __nv_bfloat16* Kl = g_l + OFF_KO;
    const __nv_bfloat16* Vh = g_h + OFF_VO; const __nv_bfloat16* Vl = g_l + OFF_VO;

    #pragma unroll
    for (int i = 0; i < 4; i++) {
        int gc = tid * 4 + i;
        int row = gc >> 3, c = gc & 7;
        size_t gi = ((size_t)(q0 + row) * B_ + b) * E_ + h * DH_ + c * 8;
        uint32_t d = sb + QH + (uint32_t)(row * 128 + ((c ^ (row & 7)) << 4));
        CP_ASYNC16(d, Qh + gi);
        CP_ASYNC16(d + (QL - QH), Ql + gi);
    }
    CP_COMMIT();

    int kvrow[2], kvc[2]; size_t kvbase[2];
    #pragma unroll
    for (int i = 0; i < 2; i++) {
        int gc = tid * 2 + i;
        kvrow[i] = gc >> 3; kvc[i] = gc & 7;
        kvbase[i] = ((size_t)kvrow[i] * B_ + b) * E_ + h * DH_ + kvc[i] * 8;
    }
    #define ISSUE_KV(t0, s) do {                                               \
        uint32_t stb = sb + STG + (uint32_t)(s) * 32768;                       \
        _Pragma("unroll")                                                      \
        for (int i = 0; i < 2; i++) {                                          \
            size_t gi = kvbase[i] + (size_t)(t0) * (B_ * E_);                  \
            uint32_t d = stb + (uint32_t)(kvrow[i] * 128 + ((kvc[i] ^ (kvrow[i] & 7)) << 4)); \
            CP_ASYNC16(d,         Kh + gi);                                    \
            CP_ASYNC16(d +  8192, Kl + gi);                                    \
            CP_ASYNC16(d + 16384, Vh + gi);                                    \
            CP_ASYNC16(d + 24576, Vl + gi);                                    \
        }                                                                      \
        CP_COMMIT();                                                           \
    } while (0)

    ISSUE_KV(0, 0);
    if (tid < 128) tq_s[tid] = td[b * S_ + q0 + tid];
    else if (tid < 192) tt_s[tid - 128] = td[b * S_ + tid - 128];
    CP_WAIT0();
    __syncthreads();

    const float tqa = tq_s[(wid << 4) + (lane >> 2)];
    const float tqb = tq_s[(wid << 4) + (lane >> 2) + 8];

    const int t8 = lane >> 3, l7 = lane & 7;
    const int qrow = (wid << 4) + ((t8 & 1) << 3) + l7;
    const int knrb = ((t8 >> 1) << 3) + l7;
    const int vtrb = ((t8 & 1) << 3) + l7;
    const int r0g = q0 + (wid << 4) + (lane >> 2);

    float m0r = -1e30f, m1r = -1e30f, l0r = 0.f, l1r = 0.f;
    float o[8][4] = {};
    __half* Pbase = g_P + ((size_t)(b * H_ + h) * S_) * S_;

    for (int tt = 0; tt < 32; tt++) {
        const int t0 = tt * 64, s = tt & 1;
        if (tt + 1 < 32) {
            ISSUE_KV(t0 + 64, s ^ 1);
            if (tid < 64) tt_s[((tt + 1) & 1) * 64 + tid] = td[b * S_ + t0 + 64 + tid];
        }
        const uint32_t KB = sb + STG + (uint32_t)s * 32768;
        const float* ttp = tt_s + s * 64;

        float sc[8][4] = {};
        #pragma unroll
        for (int ks = 0; ks < 4; ks++) {
            int qc = 2 * ks + (t8 >> 1);
            uint32_t qa = sb + QH + qrow * 128 + ((qc ^ (qrow & 7)) << 4);
            uint32_t ah[4], al[4];
            ldsm4(ah, qa); ldsm4(al, qa + (QL - QH));
            #pragma unroll
            for (int np = 0; np < 4; np++) {
                int nrow = (np << 4) + knrb;
                int kc = 2 * ks + (t8 & 1);
                uint32_t ka = KB + nrow * 128 + ((kc ^ (nrow & 7)) << 4);
                uint32_t bh[4], bl[4];
                ldsm4(bh, ka); ldsm4(bl, ka + 8192);
                mma_bf16(sc[2*np],   ah, bh[0], bh[1]);
                mma_bf16(sc[2*np],   ah, bl[0], bl[1]);
                mma_bf16(sc[2*np],   al, bh[0], bh[1]);
                mma_bf16(sc[2*np+1], ah, bh[2], bh[3]);
                mma_bf16(sc[2*np+1], ah, bl[2], bl[3]);
                mma_bf16(sc[2*np+1], al, bh[2], bh[3]);
            }
        }

        float mx0 = -1e30f, mx1 = -1e30f;
        #pragma unroll
        for (int j = 0; j < 8; j++) {
            float2 ttv = *(const float2*)&ttp[8 * j + 2 * (lane & 3)];
            float f00 = fcv * __fdividef(fbv, tqa - ttv.x + fav) + fdv;
            float f01 = fcv * __fdividef(fbv, tqa - ttv.y + fav) + fdv;
            float f10 = fcv * __fdividef(fbv, tqb - ttv.x + fav) + fdv;
            float f11 = fcv * __fdividef(fbv, tqb - ttv.y + fav) + fdv;
            sc[j][0] *= f00; sc[j][1] *= f01; sc[j][2] *= f10; sc[j][3] *= f11;
            mx0 = fmaxf(mx0, fmaxf(sc[j][0], sc[j][1]));
            mx1 = fmaxf(mx1, fmaxf(sc[j][2], sc[j][3]));
        }
        mx0 = fmaxf(mx0, __shfl_xor_sync(0xffffffffu, mx0, 1));
        mx0 = fmaxf(mx0, __shfl_xor_sync(0xffffffffu, mx0, 2));
        mx1 = fmaxf(mx1, __shfl_xor_sync(0xffffffffu, mx1, 1));
        mx1 = fmaxf(mx1, __shfl_xor_sync(0xffffffffu, mx1, 2));

        float mn0 = fmaxf(m0r, mx0), mn1 = fmaxf(m1r, mx1);
        float al0 = __expf(m0r - mn0), al1 = __expf(m1r - mn1);
        float ps0 = 0.f, ps1 = 0.f;
        #pragma unroll
        for (int j = 0; j < 8; j++) {
            sc[j][0] = __expf(sc[j][0] - mn0); sc[j][1] = __expf(sc[j][1] - mn0);
            sc[j][2] = __expf(sc[j][2] - mn1); sc[j][3] = __expf(sc[j][3] - mn1);
            ps0 += sc[j][0] + sc[j][1];
            ps1 += sc[j][2] + sc[j][3];
            int col = t0 + 8 * j + 2 * (lane & 3);
            __half2 p01 = __floats2half2_rn(sc[j][0], sc[j][1]);
            __half2 p23 = __floats2half2_rn(sc[j][2], sc[j][3]);
            stg_cs_u32(&Pbase[(size_t)r0g * S_ + col],       *(uint32_t*)&p01);
            stg_cs_u32(&Pbase[(size_t)(r0g + 8) * S_ + col], *(uint32_t*)&p23);
        }
        if ((lane & 3) == 0) {
            stg_cs_u32(&g_ml[(((size_t)b * S_ + r0g)     * H_ + h) * 32 + tt], __float_as_uint(mn0));
            stg_cs_u32(&g_ml[(((size_t)b * S_ + r0g + 8) * H_ + h) * 32 + tt], __float_as_uint(mn1));
        }
        ps0 += __shfl_xor_sync(0xffffffffu, ps0, 1); ps0 += __shfl_xor_sync(0xffffffffu, ps0, 2);
        ps1 += __shfl_xor_sync(0xffffffffu, ps1, 1); ps1 += __shfl_xor_sync(0xffffffffu, ps1, 2);
        l0r = l0r * al0 + ps0; l1r = l1r * al1 + ps1;
        m0r = mn0; m1r = mn1;
        #pragma unroll
        for (int j = 0; j < 8; j++) {
            o[j][0] *= al0; o[j][1] *= al0; o[j][2] *= al1; o[j][3] *= al1;
        }

        #pragma unroll
        for (int ks = 0; ks < 4; ks++) {
            uint32_t ah[4], alr[4];
            #pragma unroll
            for (int half = 0; half < 2; half++) {
                int jt = 2 * ks + half;
                uint32_t h0 = packbf2(sc[jt][0], sc[jt][1]);
                uint32_t h1 = packbf2(sc[jt][2], sc[jt][3]);
                float e00 = __uint_as_float(h0 << 16), e01 = __uint_as_float(h0 & 0xFFFF0000u);
                float e10 = __uint_as_float(h1 << 16), e11 = __uint_as_float(h1 & 0xFFFF0000u);
                ah [half*2]   = h0; ah [half*2+1] = h1;
                alr[half*2]   = packbf2(sc[jt][0] - e00, sc[jt][1] - e01);
                alr[half*2+1] = packbf2(sc[jt][2] - e10, sc[jt][3] - e11);
            }
            #pragma unroll
            for (int dp = 0; dp < 4; dp++) {
                int trow = (ks << 4) + vtrb;
                int dc = 2 * dp + (t8 >> 1);
                uint32_t va = KB + 16384 + trow * 128 + ((dc ^ (trow & 7)) << 4);
                uint32_t vh[4], vl[4];
                ldsm4t(vh, va); ldsm4t(vl, va + 8192);
                mma_bf16(o[2*dp],   ah,  vh[0], vh[1]);
                mma_bf16(o[2*dp],   ah,  vl[0], vl[1]);
                mma_bf16(o[2*dp],   alr, vh[0], vh[1]);
                mma_bf16(o[2*dp+1], ah,  vh[2], vh[3]);
                mma_bf16(o[2*dp+1], ah,  vl[2], vl[3]);
                mma_bf16(o[2*dp+1], alr, vh[2], vh[3]);
            }
        }

        if (tt + 1 < 32) CP_WAIT0();
        __syncthreads();
    }
    #undef ISSUE_KV

    float il0 = 1.0f / l0r, il1 = 1.0f / l1r;
    #pragma unroll
    for (int j = 0; j < 8; j++) {
        int d = h * DH_ + 8 * j + 2 * (lane & 3);
        float p0 = o[j][0] * il0, p1 = o[j][1] * il0;
        float p2 = o[j][2] * il1, p3 = o[j][3] * il1;
        uint32_t h0 = packbf2(p0, p1), h1 = packbf2(p2, p3);
        float e00 = __uint_as_float(h0 << 16), e01 = __uint_as_float(h0 & 0xFFFF0000u);
        float e10 = __uint_as_float(h1 << 16), e11 = __uint_as_float(h1 & 0xFFFF0000u);
        uint32_t l0v = packbf2(p0 - e00, p1 - e01);
        uint32_t l1v = packbf2(p2 - e10, p3 - e11);
        size_t i0 = ((size_t)r0g * B_ + b) * E_ + d;
        size_t i1 = ((size_t)(r0g + 8) * B_ + b) * E_ + d;
        *(uint32_t*)&g_h[OFF_AT + i0] = h0; *(uint32_t*)&g_l[OFF_AT + i0] = l0v;
        *(uint32_t*)&g_h[OFF_AT + i1] = h1; *(uint32_t*)&g_l[OFF_AT + i1] = l1v;
    }
    if ((lane & 3) == 0) {
        size_t base = (size_t)(b * H_ + h) * S_;
        g_m [base + r0g]     = m0r; g_il[base + r0g]     = il0;
        g_m [base + r0g + 8] = m1r; g_il[base + r0g + 8] = il1;
    }
}

// ---------------------------------------------------------------------------
extern "C" void kernel_launch(void* const* d_in, const int* in_sizes, int n_in,
                              void* d_out, int out_size)
{
    const float* query = (const float*)d_in[0];
    const float* key_t = (const float*)d_in[1];
    const float* value = (const float*)d_in[2];
    const float* td    = (const float*)d_in[3];
    const float* q_w   = (const float*)d_in[4];
    const float* k_w   = (const float*)d_in[5];
    const float* v_w   = (const float*)d_in[6];
    const float* out_w = (const float*)d_in[7];
    const float* out_b = (const float*)d_in[8];
    const float* fa    = (const float*)d_in[9];
    const float* fb    = (const float*)d_in[10];
    const float* fc    = (const float*)d_in[11];
    const float* fd    = (const float*)d_in[12];

    float* Z    = (float*)d_out;                        // [S,B,E]
    float* avgw = (float*)d_out + (size_t)S_ * B_ * E_; // [B,S,S]

    const int smem_attn = 99328;
    const int smem_gemm = 81920;
    cudaFuncSetAttribute(attn_fused_mma, cudaFuncAttributeMaxDynamicSharedMemorySize, smem_attn);
    cudaFuncSetAttribute(proj3_cp,    cudaFuncAttributeMaxDynamicSharedMemorySize, smem_gemm);
    cudaFuncSetAttribute(out_and_avg, cudaFuncAttributeMaxDynamicSharedMemorySize, smem_gemm);

    // all 7 fp32->bf16 hi/lo splits in one launch
    const int total_chunks = 3 * (MR_ * E_ / 8) + 4 * (E_ * E_ / 8);   // 2097152
    split_all<<<total_chunks / 256, 256>>>(query, key_t, value, q_w, k_w, v_w, out_w);
    // Q,K,V projections -> bf16 hi/lo pools (R12-frozen schedule, 2 blocks/SM)
    proj3_cp<<<dim3(E_ / 128, MR_ / 128, 3), 256, smem_gemm>>>();
    // fused flash attention (pool-native, double-buffered K/V, streaming P)
    attn_fused_mma<<<dim3(S_ / 128, H_, B_), 256, smem_attn>>>(td, fa, fb, fc, fd);
    // output projection + head-averaged weights (2 rows/block), co-scheduled
    out_and_avg<<<256 + S_ * B_ / 2, 256, smem_gemm>>>(out_b, Z, avgw);
}